// round 16
// baseline (speedup 1.0000x reference)
#include <cuda_runtime.h>
#include <cuda_bf16.h>
#include <cstdint>
#include <cstddef>

#define NE 50000

typedef unsigned long long ull;

// ---------------- fp32 scratch (GEMM outputs) ---------------------------------
__device__ float g_pre[NE * 128];
__device__ float g_rad[NE * 3072];
__device__ float g_c0 [NE * 1152];
__device__ float g_c1 [NE * 2048];   // (2E, 1024)
__device__ float g_c2 [NE * 1536];   // (2E, 768)
__device__ float g_d0 [NE * 640];
__device__ float g_d1 [NE * 2048];   // (2E, 1024)
__device__ float g_d2 [NE * 1536];   // (2E, 768)

// ---------------- tf32-rounded fp32 activations (GEMM A operands) -------------
__device__ float g_xe[NE * 128];
__device__ float g_h [NE * 128];
__device__ float g_x0[NE * 1280];
__device__ float g_x1[NE * 2048];    // (2E, 1024)
__device__ float g_x2[NE * 1536];    // (2E, 768)
__device__ float g_u0[NE * 640];
__device__ float g_u1[NE * 1024];    // (2E, 512)
__device__ float g_u2[NE * 768];     // (2E, 384)

// ---------------- tf32-rounded weight arena -----------------------------------
#define W_R1  0
#define W_R2  16384
#define W_01  409600
#define W_M11 1884160
#define W_M21 2932736
#define W_02  3522560
#define W_M12 3932160
#define W_M22 4456448
__device__ float g_wq[4751360];

// ---------------- helpers -----------------------------------------------------
__device__ __forceinline__ uint32_t smem_u32(const void* p) {
    uint32_t a;
    asm("{ .reg .u64 t; cvta.to.shared.u64 t, %1; cvt.u32.u64 %0, t; }" : "=r"(a) : "l"(p));
    return a;
}
__device__ __forceinline__ float tf32r(float v) {
    uint32_t u;
    asm("cvt.rna.tf32.f32 %0, %1;" : "=r"(u) : "f"(v));
    return __uint_as_float(u);
}
__device__ __forceinline__ void cpa16(uint32_t dst, const void* src) {
    asm volatile("cp.async.cg.shared.global [%0], [%1], 16;" :: "r"(dst), "l"(src));
}

#define LDSM4(r, a) \
    asm volatile("ldmatrix.sync.aligned.m8n8.x4.shared.b16 {%0,%1,%2,%3}, [%4];" \
        : "=r"((r)[0]), "=r"((r)[1]), "=r"((r)[2]), "=r"((r)[3]) : "r"(a))

#define MMA8(d, a, b0_, b1_) \
    asm volatile("mma.sync.aligned.m16n8k8.row.col.f32.tf32.tf32.f32 " \
        "{%0,%1,%2,%3},{%4,%5,%6,%7},{%8,%9},{%0,%1,%2,%3};" \
        : "+f"((d)[0]), "+f"((d)[1]), "+f"((d)[2]), "+f"((d)[3]) \
        : "r"((a)[0]), "r"((a)[1]), "r"((a)[2]), "r"((a)[3]), "r"(b0_), "r"(b1_))

// ---------------- tf32 single-pass GEMM (R10 config, unchanged) ---------------
#define TILE_SM 8192
#define STAGE_SM (2 * TILE_SM)
#define NST 3
#define SMEM_SZ (NST * STAGE_SM)

__device__ __forceinline__ uint32_t swz(uint32_t row, uint32_t cbyte) {
    return row * 64 + (cbyte ^ (((row >> 1) & 3) << 4));
}

__global__ __launch_bounds__(256, 2)
void tcgemm(const float* __restrict__ A, const float* __restrict__ W,
            const float* __restrict__ bias, float* __restrict__ C,
            int M, int N, int K)
{
    extern __shared__ char sm[];
    const uint32_t smb = smem_u32(sm);

    const int tid  = threadIdx.x;
    const int lane = tid & 31;
    const int warp = tid >> 5;
    const int wm   = warp >> 1;
    const int wn   = warp & 1;
    const int m0   = blockIdx.y * 128;
    const int n0   = blockIdx.x * 128;
    const int nch  = K >> 4;

    const char* gbase[4];
    uint32_t    soff[4];
#pragma unroll
    for (int i = 0; i < 4; i++) {
        int idx  = tid + i * 256;
        int tile = idx >> 9;
        int rem  = idx & 511;
        int row  = rem >> 2;
        int c4   = rem & 3;
        soff[i]  = (uint32_t)(tile * TILE_SM) + swz((uint32_t)row, (uint32_t)(c4 * 16));
        const float* src;
        int gr;
        if (tile == 0) { gr = m0 + row; if (gr >= M) gr = M - 1; src = A; }
        else           { gr = n0 + row; src = W; }
        gbase[i] = (const char*)(src + (size_t)gr * K) + c4 * 16;
    }

#define LOAD_STAGE(s, chunk) do {                                          \
    uint32_t sb_ = smb + (uint32_t)(s) * STAGE_SM;                         \
    int go_ = (chunk) * 64;                                                \
    cpa16(sb_ + soff[0], gbase[0] + go_);                                  \
    cpa16(sb_ + soff[1], gbase[1] + go_);                                  \
    cpa16(sb_ + soff[2], gbase[2] + go_);                                  \
    cpa16(sb_ + soff[3], gbase[3] + go_);                                  \
    asm volatile("cp.async.commit_group;" ::: "memory");                   \
} while (0)

    LOAD_STAGE(0, 0);
    LOAD_STAGE(1, 1);

    const int aRow = wm * 32 + (lane & 15);
    const int aCol = (lane >> 4) << 4;
    const int bRow = wn * 64 + (lane & 7) + ((lane >> 4) << 3);
    const int bCol = (lane & 8) << 1;

    float acc[2][8][4];
#pragma unroll
    for (int a = 0; a < 2; a++)
#pragma unroll
        for (int b = 0; b < 8; b++)
#pragma unroll
            for (int c = 0; c < 4; c++) acc[a][b][c] = 0.f;

    for (int kc = 0; kc < nch; kc++) {
        if (kc == nch - 1) asm volatile("cp.async.wait_group 0;" ::: "memory");
        else               asm volatile("cp.async.wait_group 1;" ::: "memory");
        __syncthreads();

        const int j = kc + 2;
        if (j < nch) LOAD_STAGE(j % NST, j);

        const uint32_t sb = smb + (uint32_t)(kc % NST) * STAGE_SM;
#pragma unroll
        for (int ks = 0; ks < 2; ks++) {
            const int kb = ks * 32;
            uint32_t af[2][4];
#pragma unroll
            for (int mi = 0; mi < 2; mi++) {
                uint32_t ra = sb + swz((uint32_t)(aRow + mi * 16), (uint32_t)(kb + aCol));
                LDSM4(af[mi], ra);
            }
#pragma unroll
            for (int np = 0; np < 4; np++) {
                uint32_t rb = sb + TILE_SM + swz((uint32_t)(bRow + np * 16), (uint32_t)(kb + bCol));
                uint32_t bf_[4];
                LDSM4(bf_, rb);
#pragma unroll
                for (int mi = 0; mi < 2; mi++) {
                    MMA8(acc[mi][np * 2],     af[mi], bf_[0], bf_[1]);
                    MMA8(acc[mi][np * 2 + 1], af[mi], bf_[2], bf_[3]);
                }
            }
        }
    }

#pragma unroll
    for (int mi = 0; mi < 2; mi++) {
        int r0 = m0 + wm * 32 + mi * 16 + (lane >> 2);
#pragma unroll
        for (int nf = 0; nf < 8; nf++) {
            int col = n0 + wn * 64 + nf * 8 + (lane & 3) * 2;
            float b0 = bias ? bias[col]     : 0.f;
            float b1 = bias ? bias[col + 1] : 0.f;
            if (r0 < M) {
                float2 v = make_float2(acc[mi][nf][0] + b0, acc[mi][nf][1] + b1);
                *(float2*)(C + (size_t)r0 * N + col) = v;
            }
            if (r0 + 8 < M) {
                float2 v = make_float2(acc[mi][nf][2] + b0, acc[mi][nf][3] + b1);
                *(float2*)(C + (size_t)(r0 + 8) * N + col) = v;
            }
        }
    }
}

// ---------------- fused tf32 rounding of all weights + x_edge -----------------
struct QSeg { const float* src; float* dst; int len; };
struct QArgs { QSeg seg[9]; };

__global__ __launch_bounds__(256)
void k_tf32_all(QArgs a)
{
    __shared__ int s_seg, s_base;
    if (threadIdx.x == 0) {
        int b = blockIdx.x * 256;
        int acc = 0, seg = 0, base = 0;
#pragma unroll
        for (int i = 0; i < 9; i++) {
            if (b >= acc && b < acc + a.seg[i].len) { seg = i; base = acc; }
            acc += a.seg[i].len;
        }
        s_seg = seg; s_base = base;
    }
    __syncthreads();
    int seg = s_seg;
    int off = blockIdx.x * 256 - s_base + threadIdx.x;
    if (off < a.seg[seg].len)
        a.seg[seg].dst[off] = tf32r(a.seg[seg].src[off]);
}

// ---------------- LayerNorm + SiLU -> tf32 ------------------------------------
__global__ __launch_bounds__(128)
void k_ln_silu(const float* __restrict__ pre, const float* __restrict__ gam,
               const float* __restrict__ bet)
{
    int e = blockIdx.x, t = threadIdx.x;
    float v = pre[(size_t)e * 128 + t];
    __shared__ float s1[4], s2[4];
    float a = v, a2 = v * v;
#pragma unroll
    for (int o = 16; o > 0; o >>= 1) {
        a  += __shfl_xor_sync(0xffffffffu, a,  o);
        a2 += __shfl_xor_sync(0xffffffffu, a2, o);
    }
    int w = t >> 5;
    if ((t & 31) == 0) { s1[w] = a; s2[w] = a2; }
    __syncthreads();
    float sum = s1[0] + s1[1] + s1[2] + s1[3];
    float sq  = s2[0] + s2[1] + s2[2] + s2[3];
    float mu  = sum * (1.f / 128.f);
    float var = sq * (1.f / 128.f) - mu * mu;
    if (var < 0.f) var = 0.f;
    float h = (v - mu) * rsqrtf(var + 1e-5f) * gam[t] + bet[t];
    float o = h / (1.f + expf(-h));
    g_h[(size_t)e * 128 + t] = tf32r(o);
}

// ---------------- rotation 1: per-edge tensor-core mma (R15 proven) -----------
__global__ __launch_bounds__(256)
void k_rot1(const float* __restrict__ x, const float* __restrict__ wigner,
            const int* __restrict__ edge_index)
{
    __shared__ float wa[32][36];
    __shared__ float xs[32][264];

    const int e    = blockIdx.x;
    const int tid  = threadIdx.x;
    const int lane = tid & 31;
    const int warp = tid >> 5;
    const int nb   = warp * 32;
    const int PERM_[19] = {0,2,6,11,16, 3,7,12,17, 1,5,10,15, 8,13,18, 4,9,14};

    for (int t = tid; t < 32 * 36; t += 256)
        ((float*)wa)[t] = 0.f;
    for (int t = tid; t < 7 * 264; t += 256)
        ((float*)&xs[25][0])[t] = 0.f;

    for (int t = tid; t < 19 * 25; t += 256) {
        int p = t / 25, j = t - p * 25;
        int k = PERM_[p];
        int om = k + (k >= 9 ? 1 : 0) + (k >= 14 ? 3 : 0);
        wa[p][j] = tf32r(wigner[(size_t)e * 625 + om * 25 + j]);
    }

    {
        int src = edge_index[e];
        int dst = edge_index[NE + e];
        const float* xp = x + (size_t)(tid < 128 ? src : dst) * 3200 + (tid & 127);
#pragma unroll 5
        for (int j = 0; j < 25; j++)
            xs[j][tid] = tf32r(xp[j * 128]);
    }
    __syncthreads();

    float acc[2][4][4];
#pragma unroll
    for (int a = 0; a < 2; a++)
#pragma unroll
        for (int b = 0; b < 4; b++)
#pragma unroll
            for (int c = 0; c < 4; c++) acc[a][b][c] = 0.f;

    const int q  = lane >> 2;
    const int r4 = lane & 3;

#pragma unroll
    for (int kc = 0; kc < 4; kc++) {
        const int k0 = kc * 8;
        uint32_t af[2][4];
#pragma unroll
        for (int mi = 0; mi < 2; mi++) {
            int row = mi * 16 + q;
            af[mi][0] = __float_as_uint(wa[row]    [k0 + r4]);
            af[mi][1] = __float_as_uint(wa[row + 8][k0 + r4]);
            af[mi][2] = __float_as_uint(wa[row]    [k0 + 4 + r4]);
            af[mi][3] = __float_as_uint(wa[row + 8][k0 + 4 + r4]);
        }
#pragma unroll
        for (int n8 = 0; n8 < 4; n8++) {
            int col = nb + n8 * 8 + q;
            uint32_t b0 = __float_as_uint(xs[k0 + r4]    [col]);
            uint32_t b1 = __float_as_uint(xs[k0 + 4 + r4][col]);
            MMA8(acc[0][n8], af[0], b0, b1);
            MMA8(acc[1][n8], af[1], b0, b1);
        }
    }

    const float* radp = g_rad + (size_t)e * 3072;
#pragma unroll
    for (int mi = 0; mi < 2; mi++) {
#pragma unroll
        for (int half = 0; half < 2; half++) {
            int p = mi * 16 + q + half * 8;
            if (p >= 19) continue;
            int ro;
            float* dst0;
            size_t ibase;
            if (p < 5) {
                ro = p * 256;
                ibase = (size_t)e * 1280 + p * 256;
                dst0 = g_x0;
            } else if (p < 13) {
                int s = (p - 5) & 3, rr = (p - 5) >> 2;
                ro = 1280 + s * 256;
                ibase = ((size_t)e * 2 + rr) * 1024 + s * 256;
                dst0 = g_x1;
            } else {
                int s = (p - 13) % 3, rr = (p - 13) / 3;
                ro = 2304 + s * 256;
                ibase = ((size_t)e * 2 + rr) * 768 + s * 256;
                dst0 = g_x2;
            }
#pragma unroll
            for (int n8 = 0; n8 < 4; n8++) {
                int cc = nb + n8 * 8 + r4 * 2;
                dst0[ibase + cc]     = tf32r(acc[mi][n8][half * 2]     * radp[ro + cc]);
                dst0[ibase + cc + 1] = tf32r(acc[mi][n8][half * 2 + 1] * radp[ro + cc + 1]);
            }
        }
    }
}

// ---------------- assemble conv1 out + gating -> tf32 conv2 inputs ------------
__global__ __launch_bounds__(128)
void k_assemble1()
{
    int e = blockIdx.x, c = threadIdx.x;
    const float* c0 = g_c0 + (size_t)e * 1152;

    float gate[4];
#pragma unroll
    for (int l = 0; l < 4; l++) gate[l] = 1.f / (1.f + expf(-c0[l * 128 + c]));

#pragma unroll
    for (int p = 0; p < 5; p++) {
        float v = c0[512 + p * 128 + c];
        if (p == 0) v = v / (1.f + expf(-v));
        else        v *= gate[p - 1];
        g_u0[(size_t)e * 640 + p * 128 + c] = tf32r(v);
    }

    const float* c1a = g_c1 + (size_t)e * 2048;
    const float* c1b = c1a + 1024;
#pragma unroll
    for (int s = 0; s < 4; s++) {
        float yr0 = c1a[s * 128 + c], yi0 = c1a[512 + s * 128 + c];
        float yr1 = c1b[s * 128 + c], yi1 = c1b[512 + s * 128 + c];
        g_u1[((size_t)e * 2 + 0) * 512 + s * 128 + c] = tf32r((yr0 - yi1) * gate[s]);
        g_u1[((size_t)e * 2 + 1) * 512 + s * 128 + c] = tf32r((yr1 + yi0) * gate[s]);
    }

    const float* c2a = g_c2 + (size_t)e * 1536;
    const float* c2b = c2a + 768;
#pragma unroll
    for (int s = 0; s < 3; s++) {
        float yr0 = c2a[s * 128 + c], yi0 = c2a[384 + s * 128 + c];
        float yr1 = c2b[s * 128 + c], yi1 = c2b[384 + s * 128 + c];
        g_u2[((size_t)e * 2 + 0) * 384 + s * 128 + c] = tf32r((yr0 - yi1) * gate[s + 1]);
        g_u2[((size_t)e * 2 + 1) * 384 + s * 128 + c] = tf32r((yr1 + yi0) * gate[s + 1]);
    }
}

// ---------------- rotation 2: per-edge tensor-core mma ------------------------
// out_rows[25x128] = WI[25x19] @ VAL[19x128] per edge; M pad 32, K pad 24.
// wa2 stride 28: A-load banks (28q+r4) mod 32 distinct. vs stride 136: B banks
// 8*r4+q distinct. K pad rows/cols zeroed; M pad guarded by i<25.
__global__ __launch_bounds__(128)
void k_rot2(const float* __restrict__ wigner_inv, const float* __restrict__ edist,
            const int* __restrict__ edge_index, const int* __restrict__ node_off,
            float* __restrict__ out)
{
    __shared__ float wa2[32][28];    // [i][p]
    __shared__ float vs[24][136];    // [p][c]

    const int e    = blockIdx.x;
    const int tid  = threadIdx.x;
    const int lane = tid & 31;
    const int warp = tid >> 5;
    const int nb   = warp * 32;
    const int PERM_[19] = {0,2,6,11,16, 3,7,12,17, 1,5,10,15, 8,13,18, 4,9,14};

    for (int t = tid; t < 32 * 28; t += 128)
        ((float*)wa2)[t] = 0.f;
    for (int t = tid; t < 5 * 136; t += 128)
        ((float*)&vs[19][0])[t] = 0.f;

    // wa2[i][p] = wigner_inv[e][i*25 + om(PERM p)]
    for (int t = tid; t < 19 * 25; t += 128) {
        int p = t / 25, i = t - p * 25;
        int k = PERM_[p];
        int om = k + (k >= 9 ? 1 : 0) + (k >= 14 ? 3 : 0);
        wa2[i][p] = tf32r(wigner_inv[(size_t)e * 625 + i * 25 + om]);
    }

    float d = edist[e] * (1.f / 6.f);
    float env = 0.f;
    if (d < 1.f) {
        float d2 = d * d, d4 = d2 * d2, d5 = d4 * d;
        env = 1.f + d5 * (-21.f + d * (35.f - 15.f * d));
    }

    const float* d0  = g_d0 + (size_t)e * 640;
    const float* d1a = g_d1 + (size_t)e * 2048; const float* d1b = d1a + 1024;
    const float* d2a = g_d2 + (size_t)e * 1536; const float* d2b = d2a + 768;

#pragma unroll
    for (int p = 0; p < 19; p++) {
        float v;
        if (p < 5) {
            v = d0[p * 128 + tid];
        } else if (p < 13) {
            int s = (p - 5) & 3, rr = (p - 5) >> 2;
            v = (rr == 0) ? d1a[s * 128 + tid] - d1b[512 + s * 128 + tid]
                          : d1b[s * 128 + tid] + d1a[512 + s * 128 + tid];
        } else {
            int s = (p - 13) % 3, rr = (p - 13) / 3;
            v = (rr == 0) ? d2a[s * 128 + tid] - d2b[384 + s * 128 + tid]
                          : d2b[s * 128 + tid] + d2a[384 + s * 128 + tid];
        }
        vs[p][tid] = tf32r(v * env);
    }
    __syncthreads();

    float acc[2][4][4];
#pragma unroll
    for (int a = 0; a < 2; a++)
#pragma unroll
        for (int b = 0; b < 4; b++)
#pragma unroll
            for (int c = 0; c < 4; c++) acc[a][b][c] = 0.f;

    const int q  = lane >> 2;
    const int r4 = lane & 3;

#pragma unroll
    for (int kc = 0; kc < 3; kc++) {
        const int k0 = kc * 8;
        uint32_t af[2][4];
#pragma unroll
        for (int mi = 0; mi < 2; mi++) {
            int row = mi * 16 + q;
            af[mi][0] = __float_as_uint(wa2[row]    [k0 + r4]);
            af[mi][1] = __float_as_uint(wa2[row + 8][k0 + r4]);
            af[mi][2] = __float_as_uint(wa2[row]    [k0 + 4 + r4]);
            af[mi][3] = __float_as_uint(wa2[row + 8][k0 + 4 + r4]);
        }
#pragma unroll
        for (int n8 = 0; n8 < 4; n8++) {
            int col = nb + n8 * 8 + q;
            uint32_t b0 = __float_as_uint(vs[k0 + r4]    [col]);
            uint32_t b1 = __float_as_uint(vs[k0 + 4 + r4][col]);
            MMA8(acc[0][n8], af[0], b0, b1);
            MMA8(acc[1][n8], af[1], b0, b1);
        }
    }

    int nd = edge_index[NE + e] - node_off[0];
    float* op = out + (size_t)nd * 3200;
#pragma unroll
    for (int mi = 0; mi < 2; mi++) {
#pragma unroll
        for (int half = 0; half < 2; half++) {
            int i = mi * 16 + q + half * 8;
            if (i >= 25) continue;
#pragma unroll
            for (int n8 = 0; n8 < 4; n8++) {
                int cc = nb + n8 * 8 + r4 * 2;
                atomicAdd(op + i * 128 + cc,     acc[mi][n8][half * 2]);
                atomicAdd(op + i * 128 + cc + 1, acc[mi][n8][half * 2 + 1]);
            }
        }
    }
}

// ---------------- host launch -------------------------------------------------
extern "C" void kernel_launch(void* const* d_in, const int* in_sizes, int n_in,
                              void* d_out, int out_size)
{
    const float* x          = (const float*)d_in[0];
    const float* x_edge     = (const float*)d_in[1];
    const float* edist      = (const float*)d_in[2];
    const float* wigner     = (const float*)d_in[3];
    const float* wigner_inv = (const float*)d_in[4];
    const float* W_r1       = (const float*)d_in[5];
    const float* b_r1       = (const float*)d_in[6];
    const float* ln_g       = (const float*)d_in[7];
    const float* ln_b       = (const float*)d_in[8];
    const float* W_r2       = (const float*)d_in[9];
    const float* b_r2       = (const float*)d_in[10];
    const float* W0_1       = (const float*)d_in[11];
    const float* b0_1       = (const float*)d_in[12];
    const float* Wm1_1      = (const float*)d_in[13];
    const float* Wm2_1      = (const float*)d_in[14];
    const float* W0_2       = (const float*)d_in[15];
    const float* b0_2       = (const float*)d_in[16];
    const float* Wm1_2      = (const float*)d_in[17];
    const float* Wm2_2      = (const float*)d_in[18];
    const int*   eidx       = (const int*)d_in[19];
    const int*   noff       = (const int*)d_in[20];
    float*       out        = (float*)d_out;

    cudaFuncSetAttribute(tcgemm, cudaFuncAttributeMaxDynamicSharedMemorySize, SMEM_SZ);

    float *pre, *rad, *c0, *c1, *c2, *dd0, *dd1, *dd2;
    float *xe, *hh, *x0, *x1, *x2, *u0, *u1, *u2, *wq;
    cudaGetSymbolAddress((void**)&pre, g_pre);
    cudaGetSymbolAddress((void**)&rad, g_rad);
    cudaGetSymbolAddress((void**)&c0,  g_c0);
    cudaGetSymbolAddress((void**)&c1,  g_c1);
    cudaGetSymbolAddress((void**)&c2,  g_c2);
    cudaGetSymbolAddress((void**)&dd0, g_d0);
    cudaGetSymbolAddress((void**)&dd1, g_d1);
    cudaGetSymbolAddress((void**)&dd2, g_d2);
    cudaGetSymbolAddress((void**)&xe,  g_xe);
    cudaGetSymbolAddress((void**)&hh,  g_h);
    cudaGetSymbolAddress((void**)&x0,  g_x0);
    cudaGetSymbolAddress((void**)&x1,  g_x1);
    cudaGetSymbolAddress((void**)&x2,  g_x2);
    cudaGetSymbolAddress((void**)&u0,  g_u0);
    cudaGetSymbolAddress((void**)&u1,  g_u1);
    cudaGetSymbolAddress((void**)&u2,  g_u2);
    cudaGetSymbolAddress((void**)&wq,  g_wq);

    // memset of out first: fully overlapped long before rot2 runs
    cudaMemsetAsync(d_out, 0, (size_t)out_size * sizeof(float), 0);

    // single fused tf32-rounding launch (all weights + x_edge)
    {
        QArgs qa;
        qa.seg[0] = { W_r1,   wq + W_R1,  16384 };
        qa.seg[1] = { W_r2,   wq + W_R2,  393216 };
        qa.seg[2] = { W0_1,   wq + W_01,  1474560 };
        qa.seg[3] = { Wm1_1,  wq + W_M11, 1048576 };
        qa.seg[4] = { Wm2_1,  wq + W_M21, 589824 };
        qa.seg[5] = { W0_2,   wq + W_02,  409600 };
        qa.seg[6] = { Wm1_2,  wq + W_M12, 524288 };
        qa.seg[7] = { Wm2_2,  wq + W_M22, 294912 };
        qa.seg[8] = { x_edge, xe,         NE * 128 };
        int total = 16384 + 393216 + 1474560 + 1048576 + 589824 + 409600
                  + 524288 + 294912 + NE * 128;     // 11 151 360
        k_tf32_all<<<(total + 255) / 256, 256>>>(qa);
    }

    const int gy1 = (NE + 127) / 128;            // 391
    const int gy2 = (2 * NE + 127) / 128;        // 782

    // radial MLP
    tcgemm<<<dim3(1, gy1), 256, SMEM_SZ>>>(xe, wq + W_R1, b_r1, pre, NE, 128, 128);
    k_ln_silu<<<NE, 128>>>(pre, ln_g, ln_b);
    tcgemm<<<dim3(24, gy1), 256, SMEM_SZ>>>(hh, wq + W_R2, b_r2, rad, NE, 3072, 128);

    // gather + wigner rotation + rad scaling (tensor-core mma)
    k_rot1<<<NE, 256>>>(x, wigner, eidx);

    // SO2 conv 1
    tcgemm<<<dim3(9, gy1), 256, SMEM_SZ>>>(x0, wq + W_01,  b0_1,    c0, NE,     1152, 1280);
    tcgemm<<<dim3(8, gy2), 256, SMEM_SZ>>>(x1, wq + W_M11, nullptr, c1, 2 * NE, 1024, 1024);
    tcgemm<<<dim3(6, gy2), 256, SMEM_SZ>>>(x2, wq + W_M21, nullptr, c2, 2 * NE, 768,  768);

    // gating / assembly (writes tf32)
    k_assemble1<<<NE, 128>>>();

    // SO2 conv 2
    tcgemm<<<dim3(5, gy1), 256, SMEM_SZ>>>(u0, wq + W_02,  b0_2,    dd0, NE,     640,  640);
    tcgemm<<<dim3(8, gy2), 256, SMEM_SZ>>>(u1, wq + W_M12, nullptr, dd1, 2 * NE, 1024, 512);
    tcgemm<<<dim3(6, gy2), 256, SMEM_SZ>>>(u2, wq + W_M22, nullptr, dd2, 2 * NE, 768,  384);

    // inverse rotation + envelope + scatter-add (tensor-core mma)
    k_rot2<<<NE, 128>>>(wigner_inv, edist, eidx, noff, out);
}

// round 17
// speedup vs baseline: 1.0737x; 1.0737x over previous
#include <cuda_runtime.h>
#include <cuda_bf16.h>
#include <cstdint>
#include <cstddef>

#define NE 50000

typedef unsigned long long ull;

// ---------------- fp32 scratch (GEMM outputs) ---------------------------------
__device__ float g_pre[NE * 128];
__device__ float g_rad[NE * 3072];
__device__ float g_c0 [NE * 1152];
__device__ float g_c1 [NE * 2048];   // (2E, 1024)
__device__ float g_c2 [NE * 1536];   // (2E, 768)
__device__ float g_d0 [NE * 640];
__device__ float g_d1 [NE * 2048];   // (2E, 1024)
__device__ float g_d2 [NE * 1536];   // (2E, 768)

// ---------------- tf32-rounded fp32 activations (GEMM A operands) -------------
__device__ float g_xe[NE * 128];
__device__ float g_h [NE * 128];
__device__ float g_x0[NE * 1280];
__device__ float g_x1[NE * 2048];    // (2E, 1024)
__device__ float g_x2[NE * 1536];    // (2E, 768)
__device__ float g_u0[NE * 640];
__device__ float g_u1[NE * 1024];    // (2E, 512)
__device__ float g_u2[NE * 768];     // (2E, 384)

// ---------------- tf32-rounded weight arena -----------------------------------
#define W_R1  0
#define W_R2  16384
#define W_01  409600
#define W_M11 1884160
#define W_M21 2932736
#define W_02  3522560
#define W_M12 3932160
#define W_M22 4456448
__device__ float g_wq[4751360];

// ---------------- helpers -----------------------------------------------------
__device__ __forceinline__ uint32_t smem_u32(const void* p) {
    uint32_t a;
    asm("{ .reg .u64 t; cvta.to.shared.u64 t, %1; cvt.u32.u64 %0, t; }" : "=r"(a) : "l"(p));
    return a;
}
__device__ __forceinline__ float tf32r(float v) {
    uint32_t u;
    asm("cvt.rna.tf32.f32 %0, %1;" : "=r"(u) : "f"(v));
    return __uint_as_float(u);
}
__device__ __forceinline__ void cpa16(uint32_t dst, const void* src) {
    asm volatile("cp.async.cg.shared.global [%0], [%1], 16;" :: "r"(dst), "l"(src));
}

#define LDSM4(r, a) \
    asm volatile("ldmatrix.sync.aligned.m8n8.x4.shared.b16 {%0,%1,%2,%3}, [%4];" \
        : "=r"((r)[0]), "=r"((r)[1]), "=r"((r)[2]), "=r"((r)[3]) : "r"(a))

#define MMA8(d, a, b0_, b1_) \
    asm volatile("mma.sync.aligned.m16n8k8.row.col.f32.tf32.tf32.f32 " \
        "{%0,%1,%2,%3},{%4,%5,%6,%7},{%8,%9},{%0,%1,%2,%3};" \
        : "+f"((d)[0]), "+f"((d)[1]), "+f"((d)[2]), "+f"((d)[3]) \
        : "r"((a)[0]), "r"((a)[1]), "r"((a)[2]), "r"((a)[3]), "r"(b0_), "r"(b1_))

// ---------------- tf32 single-pass GEMM, 4-stage pipeline ---------------------
#define TILE_SM 8192
#define STAGE_SM (2 * TILE_SM)
#define NST 4
#define SMEM_SZ (NST * STAGE_SM)        // 65536 B, 2 CTAs/SM

__device__ __forceinline__ uint32_t swz(uint32_t row, uint32_t cbyte) {
    return row * 64 + (cbyte ^ (((row >> 1) & 3) << 4));
}

__global__ __launch_bounds__(256, 2)
void tcgemm(const float* __restrict__ A, const float* __restrict__ W,
            const float* __restrict__ bias, float* __restrict__ C,
            int M, int N, int K)
{
    extern __shared__ char sm[];
    const uint32_t smb = smem_u32(sm);

    const int tid  = threadIdx.x;
    const int lane = tid & 31;
    const int warp = tid >> 5;
    const int wm   = warp >> 1;
    const int wn   = warp & 1;
    const int m0   = blockIdx.y * 128;
    const int n0   = blockIdx.x * 128;
    const int nch  = K >> 4;             // chunks of 16 fp32; all nch >= 8

    const char* gbase[4];
    uint32_t    soff[4];
#pragma unroll
    for (int i = 0; i < 4; i++) {
        int idx  = tid + i * 256;
        int tile = idx >> 9;
        int rem  = idx & 511;
        int row  = rem >> 2;
        int c4   = rem & 3;
        soff[i]  = (uint32_t)(tile * TILE_SM) + swz((uint32_t)row, (uint32_t)(c4 * 16));
        const float* src;
        int gr;
        if (tile == 0) { gr = m0 + row; if (gr >= M) gr = M - 1; src = A; }
        else           { gr = n0 + row; src = W; }
        gbase[i] = (const char*)(src + (size_t)gr * K) + c4 * 16;
    }

#define LOAD_STAGE(s, chunk) do {                                          \
    uint32_t sb_ = smb + (uint32_t)(s) * STAGE_SM;                         \
    int go_ = (chunk) * 64;                                                \
    cpa16(sb_ + soff[0], gbase[0] + go_);                                  \
    cpa16(sb_ + soff[1], gbase[1] + go_);                                  \
    cpa16(sb_ + soff[2], gbase[2] + go_);                                  \
    cpa16(sb_ + soff[3], gbase[3] + go_);                                  \
    asm volatile("cp.async.commit_group;" ::: "memory");                   \
} while (0)

    // prologue: 3 chunks in flight
    LOAD_STAGE(0, 0);
    LOAD_STAGE(1, 1);
    LOAD_STAGE(2, 2);

    const int aRow = wm * 32 + (lane & 15);
    const int aCol = (lane >> 4) << 4;
    const int bRow = wn * 64 + (lane & 7) + ((lane >> 4) << 3);
    const int bCol = (lane & 8) << 1;

    float acc[2][8][4];
#pragma unroll
    for (int a = 0; a < 2; a++)
#pragma unroll
        for (int b = 0; b < 8; b++)
#pragma unroll
            for (int c = 0; c < 4; c++) acc[a][b][c] = 0.f;

    for (int kc = 0; kc < nch; kc++) {
        const int rem = nch - 1 - kc;    // chunks newer than kc still pending
        if (rem >= 2)      asm volatile("cp.async.wait_group 2;" ::: "memory");
        else if (rem == 1) asm volatile("cp.async.wait_group 1;" ::: "memory");
        else               asm volatile("cp.async.wait_group 0;" ::: "memory");
        __syncthreads();

        const int j = kc + 3;
        if (j < nch) LOAD_STAGE(j % NST, j);

        const uint32_t sb = smb + (uint32_t)(kc % NST) * STAGE_SM;
#pragma unroll
        for (int ks = 0; ks < 2; ks++) {
            const int kb = ks * 32;
            uint32_t af[2][4];
#pragma unroll
            for (int mi = 0; mi < 2; mi++) {
                uint32_t ra = sb + swz((uint32_t)(aRow + mi * 16), (uint32_t)(kb + aCol));
                LDSM4(af[mi], ra);
            }
#pragma unroll
            for (int np = 0; np < 4; np++) {
                uint32_t rb = sb + TILE_SM + swz((uint32_t)(bRow + np * 16), (uint32_t)(kb + bCol));
                uint32_t bf_[4];
                LDSM4(bf_, rb);
#pragma unroll
                for (int mi = 0; mi < 2; mi++) {
                    MMA8(acc[mi][np * 2],     af[mi], bf_[0], bf_[1]);
                    MMA8(acc[mi][np * 2 + 1], af[mi], bf_[2], bf_[3]);
                }
            }
        }
    }

#pragma unroll
    for (int mi = 0; mi < 2; mi++) {
        int r0 = m0 + wm * 32 + mi * 16 + (lane >> 2);
#pragma unroll
        for (int nf = 0; nf < 8; nf++) {
            int col = n0 + wn * 64 + nf * 8 + (lane & 3) * 2;
            float b0 = bias ? bias[col]     : 0.f;
            float b1 = bias ? bias[col + 1] : 0.f;
            if (r0 < M) {
                float2 v = make_float2(acc[mi][nf][0] + b0, acc[mi][nf][1] + b1);
                *(float2*)(C + (size_t)r0 * N + col) = v;
            }
            if (r0 + 8 < M) {
                float2 v = make_float2(acc[mi][nf][2] + b0, acc[mi][nf][3] + b1);
                *(float2*)(C + (size_t)(r0 + 8) * N + col) = v;
            }
        }
    }
}

// ---------------- fused tf32 rounding of all weights + x_edge -----------------
struct QSeg { const float* src; float* dst; int len; };
struct QArgs { QSeg seg[9]; };

__global__ __launch_bounds__(256)
void k_tf32_all(QArgs a)
{
    __shared__ int s_seg, s_base;
    if (threadIdx.x == 0) {
        int b = blockIdx.x * 256;
        int acc = 0, seg = 0, base = 0;
#pragma unroll
        for (int i = 0; i < 9; i++) {
            if (b >= acc && b < acc + a.seg[i].len) { seg = i; base = acc; }
            acc += a.seg[i].len;
        }
        s_seg = seg; s_base = base;
    }
    __syncthreads();
    int seg = s_seg;
    int off = blockIdx.x * 256 - s_base + threadIdx.x;
    if (off < a.seg[seg].len)
        a.seg[seg].dst[off] = tf32r(a.seg[seg].src[off]);
}

// ---------------- LayerNorm + SiLU -> tf32 ------------------------------------
__global__ __launch_bounds__(128)
void k_ln_silu(const float* __restrict__ pre, const float* __restrict__ gam,
               const float* __restrict__ bet)
{
    int e = blockIdx.x, t = threadIdx.x;
    float v = pre[(size_t)e * 128 + t];
    __shared__ float s1[4], s2[4];
    float a = v, a2 = v * v;
#pragma unroll
    for (int o = 16; o > 0; o >>= 1) {
        a  += __shfl_xor_sync(0xffffffffu, a,  o);
        a2 += __shfl_xor_sync(0xffffffffu, a2, o);
    }
    int w = t >> 5;
    if ((t & 31) == 0) { s1[w] = a; s2[w] = a2; }
    __syncthreads();
    float sum = s1[0] + s1[1] + s1[2] + s1[3];
    float sq  = s2[0] + s2[1] + s2[2] + s2[3];
    float mu  = sum * (1.f / 128.f);
    float var = sq * (1.f / 128.f) - mu * mu;
    if (var < 0.f) var = 0.f;
    float h = (v - mu) * rsqrtf(var + 1e-5f) * gam[t] + bet[t];
    float o = h / (1.f + expf(-h));
    g_h[(size_t)e * 128 + t] = tf32r(o);
}

// ---------------- rotation 1: per-edge tensor-core mma (R15 proven) -----------
__global__ __launch_bounds__(256)
void k_rot1(const float* __restrict__ x, const float* __restrict__ wigner,
            const int* __restrict__ edge_index)
{
    __shared__ float wa[32][36];
    __shared__ float xs[32][264];

    const int e    = blockIdx.x;
    const int tid  = threadIdx.x;
    const int lane = tid & 31;
    const int warp = tid >> 5;
    const int nb   = warp * 32;
    const int PERM_[19] = {0,2,6,11,16, 3,7,12,17, 1,5,10,15, 8,13,18, 4,9,14};

    for (int t = tid; t < 32 * 36; t += 256)
        ((float*)wa)[t] = 0.f;
    for (int t = tid; t < 7 * 264; t += 256)
        ((float*)&xs[25][0])[t] = 0.f;

    for (int t = tid; t < 19 * 25; t += 256) {
        int p = t / 25, j = t - p * 25;
        int k = PERM_[p];
        int om = k + (k >= 9 ? 1 : 0) + (k >= 14 ? 3 : 0);
        wa[p][j] = tf32r(wigner[(size_t)e * 625 + om * 25 + j]);
    }

    {
        int src = edge_index[e];
        int dst = edge_index[NE + e];
        const float* xp = x + (size_t)(tid < 128 ? src : dst) * 3200 + (tid & 127);
#pragma unroll 5
        for (int j = 0; j < 25; j++)
            xs[j][tid] = tf32r(xp[j * 128]);
    }
    __syncthreads();

    float acc[2][4][4];
#pragma unroll
    for (int a = 0; a < 2; a++)
#pragma unroll
        for (int b = 0; b < 4; b++)
#pragma unroll
            for (int c = 0; c < 4; c++) acc[a][b][c] = 0.f;

    const int q  = lane >> 2;
    const int r4 = lane & 3;

#pragma unroll
    for (int kc = 0; kc < 4; kc++) {
        const int k0 = kc * 8;
        uint32_t af[2][4];
#pragma unroll
        for (int mi = 0; mi < 2; mi++) {
            int row = mi * 16 + q;
            af[mi][0] = __float_as_uint(wa[row]    [k0 + r4]);
            af[mi][1] = __float_as_uint(wa[row + 8][k0 + r4]);
            af[mi][2] = __float_as_uint(wa[row]    [k0 + 4 + r4]);
            af[mi][3] = __float_as_uint(wa[row + 8][k0 + 4 + r4]);
        }
#pragma unroll
        for (int n8 = 0; n8 < 4; n8++) {
            int col = nb + n8 * 8 + q;
            uint32_t b0 = __float_as_uint(xs[k0 + r4]    [col]);
            uint32_t b1 = __float_as_uint(xs[k0 + 4 + r4][col]);
            MMA8(acc[0][n8], af[0], b0, b1);
            MMA8(acc[1][n8], af[1], b0, b1);
        }
    }

    const float* radp = g_rad + (size_t)e * 3072;
#pragma unroll
    for (int mi = 0; mi < 2; mi++) {
#pragma unroll
        for (int half = 0; half < 2; half++) {
            int p = mi * 16 + q + half * 8;
            if (p >= 19) continue;
            int ro;
            float* dst0;
            size_t ibase;
            if (p < 5) {
                ro = p * 256;
                ibase = (size_t)e * 1280 + p * 256;
                dst0 = g_x0;
            } else if (p < 13) {
                int s = (p - 5) & 3, rr = (p - 5) >> 2;
                ro = 1280 + s * 256;
                ibase = ((size_t)e * 2 + rr) * 1024 + s * 256;
                dst0 = g_x1;
            } else {
                int s = (p - 13) % 3, rr = (p - 13) / 3;
                ro = 2304 + s * 256;
                ibase = ((size_t)e * 2 + rr) * 768 + s * 256;
                dst0 = g_x2;
            }
#pragma unroll
            for (int n8 = 0; n8 < 4; n8++) {
                int cc = nb + n8 * 8 + r4 * 2;
                dst0[ibase + cc]     = tf32r(acc[mi][n8][half * 2]     * radp[ro + cc]);
                dst0[ibase + cc + 1] = tf32r(acc[mi][n8][half * 2 + 1] * radp[ro + cc + 1]);
            }
        }
    }
}

// ---------------- assemble conv1 out + gating -> tf32 conv2 inputs ------------
__global__ __launch_bounds__(128)
void k_assemble1()
{
    int e = blockIdx.x, c = threadIdx.x;
    const float* c0 = g_c0 + (size_t)e * 1152;

    float gate[4];
#pragma unroll
    for (int l = 0; l < 4; l++) gate[l] = 1.f / (1.f + expf(-c0[l * 128 + c]));

#pragma unroll
    for (int p = 0; p < 5; p++) {
        float v = c0[512 + p * 128 + c];
        if (p == 0) v = v / (1.f + expf(-v));
        else        v *= gate[p - 1];
        g_u0[(size_t)e * 640 + p * 128 + c] = tf32r(v);
    }

    const float* c1a = g_c1 + (size_t)e * 2048;
    const float* c1b = c1a + 1024;
#pragma unroll
    for (int s = 0; s < 4; s++) {
        float yr0 = c1a[s * 128 + c], yi0 = c1a[512 + s * 128 + c];
        float yr1 = c1b[s * 128 + c], yi1 = c1b[512 + s * 128 + c];
        g_u1[((size_t)e * 2 + 0) * 512 + s * 128 + c] = tf32r((yr0 - yi1) * gate[s]);
        g_u1[((size_t)e * 2 + 1) * 512 + s * 128 + c] = tf32r((yr1 + yi0) * gate[s]);
    }

    const float* c2a = g_c2 + (size_t)e * 1536;
    const float* c2b = c2a + 768;
#pragma unroll
    for (int s = 0; s < 3; s++) {
        float yr0 = c2a[s * 128 + c], yi0 = c2a[384 + s * 128 + c];
        float yr1 = c2b[s * 128 + c], yi1 = c2b[384 + s * 128 + c];
        g_u2[((size_t)e * 2 + 0) * 384 + s * 128 + c] = tf32r((yr0 - yi1) * gate[s + 1]);
        g_u2[((size_t)e * 2 + 1) * 384 + s * 128 + c] = tf32r((yr1 + yi0) * gate[s + 1]);
    }
}

// ---------------- rotation 2: register-resident msg + broadcast wi (R12) ------
__global__ __launch_bounds__(128)
void k_rot2(const float* __restrict__ wigner_inv, const float* __restrict__ edist,
            const int* __restrict__ edge_index, const int* __restrict__ node_off,
            float* __restrict__ out)
{
    int e = blockIdx.x, c = threadIdx.x;
    __shared__ float wi2[19][26];

    const int PERM_[19] = {0,2,6,11,16, 3,7,12,17, 1,5,10,15, 8,13,18, 4,9,14};

    for (int t = c; t < 19 * 25; t += 128) {
        int p = t / 25, i = t - p * 25;
        int k = PERM_[p];
        int om = k + (k >= 9 ? 1 : 0) + (k >= 14 ? 3 : 0);
        wi2[p][i] = wigner_inv[(size_t)e * 625 + i * 25 + om];
    }

    float d = edist[e] * (1.f / 6.f);
    float env = 0.f;
    if (d < 1.f) {
        float d2 = d * d, d4 = d2 * d2, d5 = d4 * d;
        env = 1.f + d5 * (-21.f + d * (35.f - 15.f * d));
    }

    const float* d0  = g_d0 + (size_t)e * 640;
    const float* d1a = g_d1 + (size_t)e * 2048; const float* d1b = d1a + 1024;
    const float* d2a = g_d2 + (size_t)e * 1536; const float* d2b = d2a + 768;

    float val[19];
#pragma unroll
    for (int p = 0; p < 19; p++) {
        float v;
        if (p < 5) {
            v = d0[p * 128 + c];
        } else if (p < 13) {
            int s = (p - 5) & 3, rr = (p - 5) >> 2;
            v = (rr == 0) ? d1a[s * 128 + c] - d1b[512 + s * 128 + c]
                          : d1b[s * 128 + c] + d1a[512 + s * 128 + c];
        } else {
            int s = (p - 13) % 3, rr = (p - 13) / 3;
            v = (rr == 0) ? d2a[s * 128 + c] - d2b[384 + s * 128 + c]
                          : d2b[s * 128 + c] + d2a[384 + s * 128 + c];
        }
        val[p] = v * env;
    }
    __syncthreads();

    float acc[25];
#pragma unroll
    for (int i = 0; i < 25; i++) acc[i] = 0.f;
#pragma unroll
    for (int p = 0; p < 19; p++) {
        float v = val[p];
#pragma unroll
        for (int i = 0; i < 25; i++) acc[i] += wi2[p][i] * v;
    }

    int nd = edge_index[NE + e] - node_off[0];
    float* op = out + (size_t)nd * 3200 + c;
#pragma unroll
    for (int i = 0; i < 25; i++) atomicAdd(op + i * 128, acc[i]);
}

// ---------------- host launch -------------------------------------------------
extern "C" void kernel_launch(void* const* d_in, const int* in_sizes, int n_in,
                              void* d_out, int out_size)
{
    const float* x          = (const float*)d_in[0];
    const float* x_edge     = (const float*)d_in[1];
    const float* edist      = (const float*)d_in[2];
    const float* wigner     = (const float*)d_in[3];
    const float* wigner_inv = (const float*)d_in[4];
    const float* W_r1       = (const float*)d_in[5];
    const float* b_r1       = (const float*)d_in[6];
    const float* ln_g       = (const float*)d_in[7];
    const float* ln_b       = (const float*)d_in[8];
    const float* W_r2       = (const float*)d_in[9];
    const float* b_r2       = (const float*)d_in[10];
    const float* W0_1       = (const float*)d_in[11];
    const float* b0_1       = (const float*)d_in[12];
    const float* Wm1_1      = (const float*)d_in[13];
    const float* Wm2_1      = (const float*)d_in[14];
    const float* W0_2       = (const float*)d_in[15];
    const float* b0_2       = (const float*)d_in[16];
    const float* Wm1_2      = (const float*)d_in[17];
    const float* Wm2_2      = (const float*)d_in[18];
    const int*   eidx       = (const int*)d_in[19];
    const int*   noff       = (const int*)d_in[20];
    float*       out        = (float*)d_out;

    cudaFuncSetAttribute(tcgemm, cudaFuncAttributeMaxDynamicSharedMemorySize, SMEM_SZ);

    float *pre, *rad, *c0, *c1, *c2, *dd0, *dd1, *dd2;
    float *xe, *hh, *x0, *x1, *x2, *u0, *u1, *u2, *wq;
    cudaGetSymbolAddress((void**)&pre, g_pre);
    cudaGetSymbolAddress((void**)&rad, g_rad);
    cudaGetSymbolAddress((void**)&c0,  g_c0);
    cudaGetSymbolAddress((void**)&c1,  g_c1);
    cudaGetSymbolAddress((void**)&c2,  g_c2);
    cudaGetSymbolAddress((void**)&dd0, g_d0);
    cudaGetSymbolAddress((void**)&dd1, g_d1);
    cudaGetSymbolAddress((void**)&dd2, g_d2);
    cudaGetSymbolAddress((void**)&xe,  g_xe);
    cudaGetSymbolAddress((void**)&hh,  g_h);
    cudaGetSymbolAddress((void**)&x0,  g_x0);
    cudaGetSymbolAddress((void**)&x1,  g_x1);
    cudaGetSymbolAddress((void**)&x2,  g_x2);
    cudaGetSymbolAddress((void**)&u0,  g_u0);
    cudaGetSymbolAddress((void**)&u1,  g_u1);
    cudaGetSymbolAddress((void**)&u2,  g_u2);
    cudaGetSymbolAddress((void**)&wq,  g_wq);

    // memset of out first: fully overlapped long before rot2 runs
    cudaMemsetAsync(d_out, 0, (size_t)out_size * sizeof(float), 0);

    // single fused tf32-rounding launch (all weights + x_edge)
    {
        QArgs qa;
        qa.seg[0] = { W_r1,   wq + W_R1,  16384 };
        qa.seg[1] = { W_r2,   wq + W_R2,  393216 };
        qa.seg[2] = { W0_1,   wq + W_01,  1474560 };
        qa.seg[3] = { Wm1_1,  wq + W_M11, 1048576 };
        qa.seg[4] = { Wm2_1,  wq + W_M21, 589824 };
        qa.seg[5] = { W0_2,   wq + W_02,  409600 };
        qa.seg[6] = { Wm1_2,  wq + W_M12, 524288 };
        qa.seg[7] = { Wm2_2,  wq + W_M22, 294912 };
        qa.seg[8] = { x_edge, xe,         NE * 128 };
        int total = 16384 + 393216 + 1474560 + 1048576 + 589824 + 409600
                  + 524288 + 294912 + NE * 128;     // 11 151 360
        k_tf32_all<<<(total + 255) / 256, 256>>>(qa);
    }

    const int gy1 = (NE + 127) / 128;            // 391
    const int gy2 = (2 * NE + 127) / 128;        // 782

    // radial MLP
    tcgemm<<<dim3(1, gy1), 256, SMEM_SZ>>>(xe, wq + W_R1, b_r1, pre, NE, 128, 128);
    k_ln_silu<<<NE, 128>>>(pre, ln_g, ln_b);
    tcgemm<<<dim3(24, gy1), 256, SMEM_SZ>>>(hh, wq + W_R2, b_r2, rad, NE, 3072, 128);

    // gather + wigner rotation + rad scaling (tensor-core mma)
    k_rot1<<<NE, 256>>>(x, wigner, eidx);

    // SO2 conv 1
    tcgemm<<<dim3(9, gy1), 256, SMEM_SZ>>>(x0, wq + W_01,  b0_1,    c0, NE,     1152, 1280);
    tcgemm<<<dim3(8, gy2), 256, SMEM_SZ>>>(x1, wq + W_M11, nullptr, c1, 2 * NE, 1024, 1024);
    tcgemm<<<dim3(6, gy2), 256, SMEM_SZ>>>(x2, wq + W_M21, nullptr, c2, 2 * NE, 768,  768);

    // gating / assembly (writes tf32)
    k_assemble1<<<NE, 128>>>();

    // SO2 conv 2
    tcgemm<<<dim3(5, gy1), 256, SMEM_SZ>>>(u0, wq + W_02,  b0_2,    dd0, NE,     640,  640);
    tcgemm<<<dim3(8, gy2), 256, SMEM_SZ>>>(u1, wq + W_M12, nullptr, dd1, 2 * NE, 1024, 512);
    tcgemm<<<dim3(6, gy2), 256, SMEM_SZ>>>(u2, wq + W_M22, nullptr, dd2, 2 * NE, 768,  384);

    // inverse rotation + envelope + scatter-add (scalar, R12 proven)
    k_rot2<<<NE, 128>>>(wigner_inv, edist, eidx, noff, out);
}